// round 7
// baseline (speedup 1.0000x reference)
#include <cuda_runtime.h>

// ReNet layer, R6: split the non-recurrent x@W out of the serial loop.
//   pre_v:    xWv[dir][seq][t][256p] = patch(x) @ W_v + b   (K=12, tiny)
//   serial_v: h-recurrence only (K=64), writes g_v
//   pre_h:    xWh[dir][seq][t][256p] = g_v @ W_h + b        (K=128, the big GEMM)
//   serial_h: h-recurrence only (K=64), writes output
// Serial kernels: 512 thr = 4 seq-groups x 4 hid-quarters, lane = (hid16, gatepair),
// gate halves combined via shfl.down 16. xW prefetched one step ahead.
// Permuted gate layout everywhere: pc = (h>>4)*64 + (h&15)*4 + g.

#define HIDN 64
#define NGC  256
#define BN   16
#define SJ   128
#define NSEQ 32

typedef unsigned long long ull;

__device__ float g_v[BN * SJ * SJ * 2 * HIDN];      // [b][j][i][128]   134 MB
__device__ float g_xwv[2 * BN * SJ * SJ * NGC];     // [dir][seq][t][256p] 537 MB
__device__ float g_xwh[2 * BN * SJ * SJ * NGC];     // [dir][seq][t][256p] 537 MB

__device__ __forceinline__ ull pack2(float lo, float hi) {
    ull r; asm("mov.b64 %0, {%1, %2};" : "=l"(r) : "f"(lo), "f"(hi)); return r;
}
__device__ __forceinline__ void unpack2(ull v, float& lo, float& hi) {
    asm("mov.b64 {%0, %1}, %2;" : "=f"(lo), "=f"(hi) : "l"(v));
}
__device__ __forceinline__ void ffma2(ull& d, ull a, ull b) {
    asm("fma.rn.f32x2 %0, %1, %2, %0;" : "+l"(d) : "l"(a), "l"(b));
}
__device__ __forceinline__ ull addf2(ull a, ull b) {
    ull r; asm("add.rn.f32x2 %0, %1, %2;" : "=l"(r) : "l"(a), "l"(b)); return r;
}
__device__ __forceinline__ float sigf(float x)   { return 1.0f / (1.0f + __expf(-x)); }
__device__ __forceinline__ float mytanh(float x) { return 1.0f - 2.0f / (__expf(2.0f * x) + 1.0f); }
__device__ __forceinline__ void bar_grp(int sg) {
    asm volatile("bar.sync %0, 128;" :: "r"(sg + 1) : "memory");
}

// ---------------------------------------------------------------------------
// Precompute: xw[dir][seq][t][pc] = bias + x(seq,t) @ W   (permuted cols)
// block = (dir, seq, 64-t tile, 128-col slice); 256 thr; thread: 8 rows x 4 cols
// ---------------------------------------------------------------------------
template <int DIN>
__global__ void __launch_bounds__(256, 2)
precompute_xw(const float* __restrict__ W0, const float* __restrict__ b0,
              const float* __restrict__ W1, const float* __restrict__ b1,
              const float* __restrict__ src, float* __restrict__ xw)
{
    const int bx    = blockIdx.x;
    const int slice = bx & 1;
    const int t0    = ((bx >> 1) & 1) * 64;
    const int seq   = (bx >> 2) & 2047;
    const int dir   = bx >> 13;

    extern __shared__ float smp[];
    float* sW = smp;               // [DIN][128] permuted slice
    float* sA = smp + DIN * 128;   // [64][DIN]

    const float* W  = dir ? W1 : W0;
    const float* bb = dir ? b1 : b0;
    const int tid = threadIdx.x, lane = tid & 31, w = tid >> 5;
    const int b = seq >> 7, ji = seq & 127;

    for (int idx = tid; idx < DIN * 128; idx += 256) {
        int k = idx >> 7, cl = idx & 127;
        int hl = cl >> 2, g = cl & 3;
        sW[idx] = W[k * NGC + g * 64 + slice * 32 + hl];
    }
    if (DIN == 128) {
#pragma unroll
        for (int it = 0; it < 8; it++) {
            int e = tid + 256 * it;            // 2048 float4
            int r = e >> 5, f4 = e & 31;
            int t = t0 + r;
            int i = dir ? 127 - t : t;
            *(float4*)&sA[r * 128 + f4 * 4] =
                *(const float4*)&src[((size_t)((b * 128 + ji) * 128 + i)) * 128 + f4 * 4];
        }
    } else {
        for (int e = tid; e < 64 * 12; e += 256) {
            int r = e / 12, d = e - r * 12;
            int t = t0 + r;
            int j = dir ? 127 - t : t;
            int pr = d / 6, rm = d - pr * 6;
            int pc = rm / 3, ch = rm - pc * 3;
            sA[r * 12 + d] =
                src[((b * 256 + (2 * j + pr)) * 256 + (2 * ji + pc)) * 3 + ch];
        }
    }
    __syncthreads();

    const int h = slice * 32 + lane;
    ull acc[8][2];
    {
        ull bi0 = pack2(bb[0 * 64 + h], bb[1 * 64 + h]);
        ull bi1 = pack2(bb[2 * 64 + h], bb[3 * 64 + h]);
#pragma unroll
        for (int m = 0; m < 8; m++) { acc[m][0] = bi0; acc[m][1] = bi1; }
    }

    const float* arow = sA + (w * 8) * DIN;
    const float* wb   = sW + lane * 4;
#pragma unroll 2
    for (int k = 0; k < DIN; k += 4) {
        float4 xq[8];
#pragma unroll
        for (int m = 0; m < 8; m++) xq[m] = *(const float4*)&arow[m * DIN + k];
        const float* xf = (const float*)xq;
#pragma unroll
        for (int kk = 0; kk < 4; kk++) {
            ulonglong2 w2 = *(const ulonglong2*)&wb[(k + kk) * 128];
#pragma unroll
            for (int m = 0; m < 8; m++) {
                float a = xf[m * 4 + kk];
                ull a2 = pack2(a, a);
                ffma2(acc[m][0], a2, w2.x);   // (i,f)
                ffma2(acc[m][1], a2, w2.y);   // (g,o)
            }
        }
    }

    size_t base = ((size_t)(dir * 2048 + seq) * 128 + t0) * 256 + slice * 128 + lane * 4;
#pragma unroll
    for (int m = 0; m < 8; m++) {
        int r = w * 8 + m;
        float a0, a1, a2v, a3;
        unpack2(acc[m][0], a0, a1);
        unpack2(acc[m][1], a2v, a3);
        *(float4*)&xw[base + (size_t)r * 256] = make_float4(a0, a1, a2v, a3);
    }
}

// ---------------------------------------------------------------------------
// Serial recurrence: z = xw_t + h @ U; K=64. 512 thr = 4 seq-grp x 4 hid-qtr.
// PASS 0: vertical (seq = b*128+i, writes g_v[b][t][i]); PASS 1: horizontal.
// ---------------------------------------------------------------------------
template <int PASS>
__global__ void __launch_bounds__(512, 1)
renet_serial(const float* __restrict__ Ua, const float* __restrict__ Ub,
             const float* __restrict__ xw, float* __restrict__ dst)
{
    extern __shared__ float sm[];
    float* sU = sm;               // [64][256] permuted
    float* sH = sm + 64 * NGC;    // [32][64]

    const int dir = blockIdx.x >> 6;
    const int s0  = (blockIdx.x & 63) * NSEQ;
    const int tid = threadIdx.x, lane = tid & 31, w = tid >> 5;
    const int sg = w >> 2;                    // seq group: 8 seqs (warps spread over SMSPs)
    const int q  = w & 3;                     // hid quarter
    const int hid16 = lane & 15, gp = lane >> 4;
    const int hid = q * 16 + hid16;

    const float* U = dir ? Ub : Ua;
    for (int idx = tid; idx < 64 * NGC; idx += 512) {
        int k = idx >> 8, c = idx & 255;
        int g = c >> 6, h = c & 63;
        int pc = (h >> 4) * 64 + (h & 15) * 4 + g;
        sU[k * NGC + pc] = U[idx];
    }
    for (int idx = tid; idx < 32 * 64; idx += 512) sH[idx] = 0.0f;
    __syncthreads();

    const float* xwp = xw + ((size_t)(dir * 2048 + s0 + sg * 8) * 128) * 256
                          + q * 64 + hid16 * 4 + gp * 2;
    const float* hb = sH + (sg * 8) * 64;
    const float* ub = sU + q * 64 + hid16 * 4 + gp * 2;

    float cst[8];
#pragma unroll
    for (int m = 0; m < 8; m++) cst[m] = 0.0f;

    ull xwreg[8];
#pragma unroll
    for (int m = 0; m < 8; m++) xwreg[m] = *(const ull*)&xwp[m * 32768];

    for (int t = 0; t < SJ; t++) {
        bar_grp(sg);                          // h_{t-1} visible in sH

        // prefetch xw for t+1 (overlaps GEMM)
        ull xwn[8];
        {
            int tn = (t + 1 < SJ) ? t + 1 : t;
#pragma unroll
            for (int m = 0; m < 8; m++)
                xwn[m] = *(const ull*)&xwp[m * 32768 + tn * 256];
        }

        ull acc[8];
#pragma unroll
        for (int m = 0; m < 8; m++) acc[m] = 0ull;

#pragma unroll 2
        for (int k = 0; k < 64; k += 4) {
            float4 xq[8];
#pragma unroll
            for (int m = 0; m < 8; m++) xq[m] = *(const float4*)&hb[m * 64 + k];
            const float* xf = (const float*)xq;
#pragma unroll
            for (int kk = 0; kk < 4; kk++) {
                ull wv = *(const ull*)&ub[(k + kk) * NGC];
#pragma unroll
                for (int m = 0; m < 8; m++) {
                    float a = xf[m * 4 + kk];
                    ffma2(acc[m], pack2(a, a), wv);
                }
            }
        }
        bar_grp(sg);                          // all reads of sH done

#pragma unroll
        for (int m = 0; m < 8; m++) {
            ull z = addf2(acc[m], xwreg[m]);                     // own gate pair
            ull zo2 = __shfl_down_sync(0xffffffffu, z, 16);      // partner pair
            if (gp == 0) {
                float zi, zf, zg, zo;
                unpack2(z, zi, zf);
                unpack2(zo2, zg, zo);
                float c = sigf(zf) * cst[m] + sigf(zi) * mytanh(zg);
                cst[m] = c;
                float hv = sigf(zo) * mytanh(c);

                int s = sg * 8 + m;
                sH[s * 64 + hid] = hv;

                int qq = s0 + s;
                int b = qq >> 7, ji = qq & 127;
                int row = (PASS == 0) ? t : ji;
                int col = (PASS == 0) ? ji : t;
                dst[((size_t)((b * 128 + row) * 128 + col)) * 128 + dir * 64 + hid] = hv;
            }
            xwreg[m] = xwn[m];
        }
    }
}

extern "C" void kernel_launch(void* const* d_in, const int* in_sizes, int n_in,
                              void* d_out, int out_size)
{
    const float* inputs = (const float*)d_in[0];
    const float* W_ud = (const float*)d_in[1];
    const float* U_ud = (const float*)d_in[2];
    const float* b_ud = (const float*)d_in[3];
    const float* W_du = (const float*)d_in[4];
    const float* U_du = (const float*)d_in[5];
    const float* b_du = (const float*)d_in[6];
    const float* W_lr = (const float*)d_in[7];
    const float* U_lr = (const float*)d_in[8];
    const float* b_lr = (const float*)d_in[9];
    const float* W_rl = (const float*)d_in[10];
    const float* U_rl = (const float*)d_in[11];
    const float* b_rl = (const float*)d_in[12];

    float *vbuf, *xwv, *xwh;
    cudaGetSymbolAddress((void**)&vbuf, g_v);
    cudaGetSymbolAddress((void**)&xwv, g_xwv);
    cudaGetSymbolAddress((void**)&xwh, g_xwh);

    size_t smem_pv = (size_t)(12 * 128 + 64 * 12) * sizeof(float);    //   9,216 B
    size_t smem_ph = (size_t)(128 * 128 + 64 * 128) * sizeof(float);  //  98,304 B
    size_t smem_s  = (size_t)(64 * NGC + 32 * 64) * sizeof(float);    //  73,728 B

    cudaFuncSetAttribute(precompute_xw<128>, cudaFuncAttributeMaxDynamicSharedMemorySize, (int)smem_ph);
    cudaFuncSetAttribute(renet_serial<0>, cudaFuncAttributeMaxDynamicSharedMemorySize, (int)smem_s);
    cudaFuncSetAttribute(renet_serial<1>, cudaFuncAttributeMaxDynamicSharedMemorySize, (int)smem_s);

    // 1) vertical x@W + b
    precompute_xw<12><<<16384, 256, smem_pv>>>(W_ud, b_ud, W_du, b_du, inputs, xwv);
    // 2) vertical recurrence -> g_v
    renet_serial<0><<<128, 512, smem_s>>>(U_ud, U_du, xwv, vbuf);
    // 3) horizontal x@W + b (x = g_v)
    precompute_xw<128><<<16384, 256, smem_ph>>>(W_lr, b_lr, W_rl, b_rl, vbuf, xwh);
    // 4) horizontal recurrence -> out
    renet_serial<1><<<128, 512, smem_s>>>(U_lr, U_rl, xwh, (float*)d_out);
}

// round 8
// speedup vs baseline: 1.1324x; 1.1324x over previous
#include <cuda_runtime.h>

// ReNet layer, R7: fused per-pass kernel (best-known structure, R5) with the
// f32x2 packed axis moved from column-pairs to K-PAIRS:
//   acc_c = (sum_{k even} h_k w_kc , sum_{k odd} h_k w_kc), fold lo+hi at end.
// Both FFMA2 operands now come straight out of LDS.128 register pairs
// (x: adjacent k's; w: k-pair-interleaved layout) -> ZERO pack movs.
// Lane = 1 hid x 4 gates (complete gate set locally). 256 thr = 4 seq-groups
// x 2 hid-halves; pair-local named barriers; double-buffered 4-k chunks.

#define HIDN 64
#define NGC  256
#define BN   16
#define SJ   128
#define NSEQ 32
#define NTHR 256

typedef unsigned long long ull;

__device__ float g_v[BN * SJ * SJ * 2 * HIDN];   // vertical output [B][J][I][128]

__device__ __forceinline__ void unpack2(ull v, float& lo, float& hi) {
    asm("mov.b64 {%0, %1}, %2;" : "=f"(lo), "=f"(hi) : "l"(v));
}
__device__ __forceinline__ void ffma2(ull& d, ull a, ull b) {
    asm("fma.rn.f32x2 %0, %1, %2, %0;" : "+l"(d) : "l"(a), "l"(b));
}
__device__ __forceinline__ ull pack2(float lo, float hi) {
    ull r; asm("mov.b64 %0, {%1, %2};" : "=l"(r) : "f"(lo), "f"(hi)); return r;
}
__device__ __forceinline__ float sigf(float x)   { return 1.0f / (1.0f + __expf(-x)); }
__device__ __forceinline__ float mytanh(float x) { return 1.0f - 2.0f / (__expf(2.0f * x) + 1.0f); }
__device__ __forceinline__ void bar_pair(int sg) {
    asm volatile("bar.sync %0, 64;" :: "r"(sg + 1) : "memory");
}

template <int DIN>
__global__ void __launch_bounds__(NTHR, 1)
renet_pass(const float* __restrict__ W0, const float* __restrict__ U0, const float* __restrict__ b0,
           const float* __restrict__ W1, const float* __restrict__ U1, const float* __restrict__ b1,
           const float* __restrict__ src, float* __restrict__ dst)
{
    constexpr int K   = DIN + HIDN;
    constexpr int KP  = (K + 7) & ~7;         // padded; zero pad weights + zero pad x
    constexpr int NKP = KP / 2;               // k-pairs
    extern __shared__ float sm[];
    float* sW  = sm;                   // [NKP][256] of ull: (w_even, w_odd) per col
    float* sXH = sm + KP * NGC;        // [NSEQ][KP] per-seq (x_t ++ h ++ pad)
    float* sB  = sXH + NSEQ * KP;      // [NGC]

    const int dir  = blockIdx.x >> 6;
    const int s0   = (blockIdx.x & 63) * NSEQ;
    const int tid  = threadIdx.x;
    const int lane = tid & 31;
    const int wid  = tid >> 5;
    const int hh   = wid & 1;                 // hid half
    const int sg   = wid >> 1;                // seq group: 8 seqs
    const int ptid = tid & 63;
    const int hid  = hh * 32 + lane;

    const float* W  = dir ? W1 : W0;
    const float* U  = dir ? U1 : U0;
    const float* bb = dir ? b1 : b0;

    // weight layout (as ull array): sWu[kp*256 + (hid>>5)*128 + (hid&31)*4 + g]
    //   = ( worig[2kp][g*64+hid] , worig[2kp+1][g*64+hid] )
    for (int u = tid; u < NKP * NGC; u += NTHR) {
        int kp = u >> 8, c = u & 255;
        int hq = c >> 7, l5 = (c >> 2) & 31, g = c & 3;
        int col = g * 64 + hq * 32 + l5;
        int k0 = 2 * kp, k1 = 2 * kp + 1;
        float v0 = (k0 < DIN) ? W[k0 * NGC + col] : (k0 < K) ? U[(k0 - DIN) * NGC + col] : 0.0f;
        float v1 = (k1 < DIN) ? W[k1 * NGC + col] : (k1 < K) ? U[(k1 - DIN) * NGC + col] : 0.0f;
        sW[u * 2]     = v0;
        sW[u * 2 + 1] = v1;
    }
    for (int idx = tid; idx < NGC; idx += NTHR) sB[idx] = bb[idx];
    for (int idx = tid; idx < NSEQ * (KP - DIN); idx += NTHR) {
        int s = idx / (KP - DIN), o = idx % (KP - DIN);
        sXH[s * KP + DIN + o] = 0.0f;          // h_0 = 0 and k-pad = 0
    }
    __syncthreads();

    float bgate[4];
#pragma unroll
    for (int g = 0; g < 4; g++) bgate[g] = sB[g * 64 + hid];

    float cst[8];
#pragma unroll
    for (int m = 0; m < 8; m++) cst[m] = 0.0f;

    // ---- pair-local x staging for step t into rows [8sg, 8sg+8)
    auto stage_x = [&](int t) {
        if (DIN == 12) {
            const int jin = dir ? (SJ - 1 - t) : t;
            for (int e = ptid; e < 8 * 12; e += 64) {
                int sl = e / 12, d = e - sl * 12;
                int q = s0 + sg * 8 + sl;
                int b = q >> 7, i = q & 127;
                int pr = d / 6, rm = d - pr * 6;
                int pc = rm / 3, ch = rm - pc * 3;
                sXH[(sg * 8 + sl) * KP + d] =
                    src[((b * 256 + (2 * jin + pr)) * 256 + (2 * i + pc)) * 3 + ch];
            }
        } else {
            const int iin = dir ? (SJ - 1 - t) : t;
#pragma unroll
            for (int r = 0; r < 4; r++) {
                int idx = ptid + 64 * r;       // 256 = 8 seq * 32 float4
                int sl = idx >> 5, f4 = idx & 31;
                int q = s0 + sg * 8 + sl;
                int b = q >> 7, j = q & 127;
                float4 v4 = *(const float4*)
                    &src[((size_t)((b * 128 + j) * 128 + iin)) * 128 + f4 * 4];
                *(float4*)&sXH[(sg * 8 + sl) * KP + f4 * 4] = v4;
            }
        }
    };

    stage_x(0);

    const float* xbase = sXH + (sg * 8) * KP;
    const ull*   wlane = (const ull*)sW + (size_t)(hh * 32 + lane) * 4;

    for (int t = 0; t < SJ; t++) {
        bar_pair(sg);                          // A: x_t staged, h_{t-1} visible

        // acc[m][g] = (even-k partial, odd-k partial); bias folded into lo half
        ull acc[8][4];
#pragma unroll
        for (int m = 0; m < 8; m++)
#pragma unroll
            for (int g = 0; g < 4; g++) acc[m][g] = pack2(bgate[g] * (m == m ? 1.0f : 1.0f), 0.0f);
        // (bias in lo, 0 in hi; fold at end gives bias + full sum)
#pragma unroll
        for (int m = 0; m < 8; m++)
#pragma unroll
            for (int g = 0; g < 4; g++) acc[m][g] = pack2(bgate[g], 0.0f);

        // chunk = 4 k = 2 k-pairs, double-buffered
        ulonglong2 xA[8], xB[8];               // (h_k,h_k+1),(h_k+2,h_k+3) per seq
        ulonglong2 wA[2][2], wB[2][2];         // [pair][(g0,g1)|(g2,g3)]

        auto loadx = [&](ulonglong2* xq, int k) {
#pragma unroll
            for (int m = 0; m < 8; m++)
                xq[m] = *(const ulonglong2*)&xbase[m * KP + k];
        };
        auto loadw = [&](ulonglong2 (*wq)[2], int kp) {
#pragma unroll
            for (int p = 0; p < 2; p++) {
                const ulonglong2* wp = (const ulonglong2*)(wlane + (size_t)(kp + p) * 256);
                wq[p][0] = wp[0];
                wq[p][1] = wp[1];
            }
        };
        auto chunk = [&](const ulonglong2* xq, const ulonglong2 (*wq)[2]) {
#pragma unroll
            for (int p = 0; p < 2; p++) {
#pragma unroll
                for (int m = 0; m < 8; m++) {
                    ull xh = p ? xq[m].y : xq[m].x;
                    ffma2(acc[m][0], xh, wq[p][0].x);
                    ffma2(acc[m][1], xh, wq[p][0].y);
                    ffma2(acc[m][2], xh, wq[p][1].x);
                    ffma2(acc[m][3], xh, wq[p][1].y);
                }
            }
        };

        loadx(xA, 0); loadw(wA, 0);
#pragma unroll 1
        for (int k = 0; k < KP; k += 8) {
            loadx(xB, k + 4); loadw(wB, (k + 4) >> 1);
            chunk(xA, wA);
            if (k + 8 < KP) { loadx(xA, k + 8); loadw(wA, (k + 8) >> 1); }
            chunk(xB, wB);
        }

        bar_pair(sg);                          // B: pair's reads of sXH done

#pragma unroll
        for (int m = 0; m < 8; m++) {
            float lo, hi, zi, zf, zg, zo;
            unpack2(acc[m][0], lo, hi); zi = lo + hi;
            unpack2(acc[m][1], lo, hi); zf = lo + hi;
            unpack2(acc[m][2], lo, hi); zg = lo + hi;
            unpack2(acc[m][3], lo, hi); zo = lo + hi;
            float c = sigf(zf) * cst[m] + sigf(zi) * mytanh(zg);
            cst[m] = c;
            float hv = sigf(zo) * mytanh(c);

            int s = sg * 8 + m;
            sXH[s * KP + DIN + hid] = hv;

            int q = s0 + s;
            int b = q >> 7, w = q & 127;
            int row = (DIN == 12) ? t : w;
            int col = (DIN == 12) ? w : t;
            dst[((size_t)((b * 128 + row) * 128 + col)) * 128 + dir * 64 + hid] = hv;
        }

        if (t + 1 < SJ) stage_x(t + 1);        // x region disjoint from h region
    }
}

extern "C" void kernel_launch(void* const* d_in, const int* in_sizes, int n_in,
                              void* d_out, int out_size)
{
    const float* inputs = (const float*)d_in[0];
    const float* W_ud = (const float*)d_in[1];
    const float* U_ud = (const float*)d_in[2];
    const float* b_ud = (const float*)d_in[3];
    const float* W_du = (const float*)d_in[4];
    const float* U_du = (const float*)d_in[5];
    const float* b_du = (const float*)d_in[6];
    const float* W_lr = (const float*)d_in[7];
    const float* U_lr = (const float*)d_in[8];
    const float* b_lr = (const float*)d_in[9];
    const float* W_rl = (const float*)d_in[10];
    const float* U_rl = (const float*)d_in[11];
    const float* b_rl = (const float*)d_in[12];

    float* vbuf = nullptr;
    cudaGetSymbolAddress((void**)&vbuf, g_v);

    constexpr int KP1 = 80;    // (12+64) padded to 8
    constexpr int KP2 = 192;   // 128+64
    size_t smem1 = (size_t)(KP1 * NGC + NSEQ * KP1 + NGC) * sizeof(float);  //  93,184 B
    size_t smem2 = (size_t)(KP2 * NGC + NSEQ * KP2 + NGC) * sizeof(float);  // 222,208 B

    cudaFuncSetAttribute(renet_pass<12>,  cudaFuncAttributeMaxDynamicSharedMemorySize, (int)smem1);
    cudaFuncSetAttribute(renet_pass<128>, cudaFuncAttributeMaxDynamicSharedMemorySize, (int)smem2);

    renet_pass<12><<<128, NTHR, smem1>>>(W_ud, U_ud, b_ud, W_du, U_du, b_du,
                                         inputs, vbuf);
    renet_pass<128><<<128, NTHR, smem2>>>(W_lr, U_lr, b_lr, W_rl, U_rl, b_rl,
                                          vbuf, (float*)d_out);
}

// round 9
// speedup vs baseline: 1.1816x; 1.0434x over previous
#include <cuda_runtime.h>

// ReNet layer, R8: fused per-pass kernel, K-PAIR f32x2 packing with a
// CONFLICT-FREE gate-split weight layout.
//   acc[m][g] = (sum_{even k} h_k w, sum_{odd k} h_k w); fold lo+hi at end.
//   x operand (h_k, h_{k+1}) : ulonglong2 straight from sXH (adjacent k).
//   w operand (w_2kp, w_2kp+1) per gate: per k-pair two 1KB regions
//     B0[hid] = {pair_gI, pair_gF}, B1[hid] = {pair_gG, pair_gO};
//     lane LDS.128 at hid*16B -> contiguous, conflict-free. ZERO pack movs.
// 256 thr = 4 seq-groups x 2 hid-halves; pair-local named barriers;
// double-buffered 4-k chunks. Lane owns 1 hid x all 4 gates.

#define HIDN 64
#define NGC  256
#define BN   16
#define SJ   128
#define NSEQ 32
#define NTHR 256

typedef unsigned long long ull;

__device__ float g_v[BN * SJ * SJ * 2 * HIDN];   // vertical output [B][J][I][128]

__device__ __forceinline__ void unpack2(ull v, float& lo, float& hi) {
    asm("mov.b64 {%0, %1}, %2;" : "=f"(lo), "=f"(hi) : "l"(v));
}
__device__ __forceinline__ ull pack2(float lo, float hi) {
    ull r; asm("mov.b64 %0, {%1, %2};" : "=l"(r) : "f"(lo), "f"(hi)); return r;
}
__device__ __forceinline__ void ffma2(ull& d, ull a, ull b) {
    asm("fma.rn.f32x2 %0, %1, %2, %0;" : "+l"(d) : "l"(a), "l"(b));
}
__device__ __forceinline__ float sigf(float x)   { return 1.0f / (1.0f + __expf(-x)); }
__device__ __forceinline__ float mytanh(float x) { return 1.0f - 2.0f / (__expf(2.0f * x) + 1.0f); }
__device__ __forceinline__ void bar_pair(int sg) {
    asm volatile("bar.sync %0, 64;" :: "r"(sg + 1) : "memory");
}

template <int DIN>
__global__ void __launch_bounds__(NTHR, 1)
renet_pass(const float* __restrict__ W0, const float* __restrict__ U0, const float* __restrict__ b0,
           const float* __restrict__ W1, const float* __restrict__ U1, const float* __restrict__ b1,
           const float* __restrict__ src, float* __restrict__ dst)
{
    constexpr int K   = DIN + HIDN;
    constexpr int KP  = (K + 7) & ~7;         // padded; zero pad weights + zero pad x
    constexpr int NKP = KP / 2;               // k-pairs
    extern __shared__ float sm[];
    float* sW  = sm;                   // [NKP][256] ulls: per kp {B0:64x2ull, B1:64x2ull}
    float* sXH = sm + KP * NGC;        // [NSEQ][KP] per-seq (x_t ++ h ++ pad)
    float* sB  = sXH + NSEQ * KP;      // [NGC]

    const int dir  = blockIdx.x >> 6;
    const int s0   = (blockIdx.x & 63) * NSEQ;
    const int tid  = threadIdx.x;
    const int lane = tid & 31;
    const int wid  = tid >> 5;
    const int hh   = wid & 1;                 // hid half
    const int sg   = wid >> 1;                // seq group: 8 seqs
    const int ptid = tid & 63;
    const int hid  = hh * 32 + lane;

    const float* W  = dir ? W1 : W0;
    const float* U  = dir ? U1 : U0;
    const float* bb = dir ? b1 : b0;

    // weight staging:
    // ull index u = kp*256 + gpair*128 + hid*2 + glow
    //   gate g = gpair*2 + glow; value = ( worig[2kp][g*64+hid], worig[2kp+1][g*64+hid] )
    for (int u = tid; u < NKP * 256; u += NTHR) {
        int kp = u >> 8, r = u & 255;
        int gpair = r >> 7, h = (r >> 1) & 63, glow = r & 1;
        int col = (gpair * 2 + glow) * 64 + h;
        int k0 = 2 * kp, k1 = k0 + 1;
        float v0 = (k0 < DIN) ? W[k0 * NGC + col] : (k0 < K) ? U[(k0 - DIN) * NGC + col] : 0.0f;
        float v1 = (k1 < DIN) ? W[k1 * NGC + col] : (k1 < K) ? U[(k1 - DIN) * NGC + col] : 0.0f;
        sW[u * 2]     = v0;
        sW[u * 2 + 1] = v1;
    }
    for (int idx = tid; idx < NGC; idx += NTHR) sB[idx] = bb[idx];
    for (int idx = tid; idx < NSEQ * (KP - DIN); idx += NTHR) {
        int s = idx / (KP - DIN), o = idx % (KP - DIN);
        sXH[s * KP + DIN + o] = 0.0f;          // h_0 = 0 and k-pad = 0
    }
    __syncthreads();

    ull binit[4];
#pragma unroll
    for (int g = 0; g < 4; g++) binit[g] = pack2(sB[g * 64 + hid], 0.0f);

    float cst[8];
#pragma unroll
    for (int m = 0; m < 8; m++) cst[m] = 0.0f;

    // ---- pair-local x staging for step t into rows [8sg, 8sg+8)
    auto stage_x = [&](int t) {
        if (DIN == 12) {
            const int jin = dir ? (SJ - 1 - t) : t;
            for (int e = ptid; e < 8 * 12; e += 64) {
                int sl = e / 12, d = e - sl * 12;
                int q = s0 + sg * 8 + sl;
                int b = q >> 7, i = q & 127;
                int pr = d / 6, rm = d - pr * 6;
                int pc = rm / 3, ch = rm - pc * 3;
                sXH[(sg * 8 + sl) * KP + d] =
                    src[((b * 256 + (2 * jin + pr)) * 256 + (2 * i + pc)) * 3 + ch];
            }
        } else {
            const int iin = dir ? (SJ - 1 - t) : t;
#pragma unroll
            for (int r = 0; r < 4; r++) {
                int idx = ptid + 64 * r;       // 256 = 8 seq * 32 float4
                int sl = idx >> 5, f4 = idx & 31;
                int q = s0 + sg * 8 + sl;
                int b = q >> 7, j = q & 127;
                float4 v4 = *(const float4*)
                    &src[((size_t)((b * 128 + j) * 128 + iin)) * 128 + f4 * 4];
                *(float4*)&sXH[(sg * 8 + sl) * KP + f4 * 4] = v4;
            }
        }
    };

    stage_x(0);

    const float* xbase = sXH + (sg * 8) * KP;
    const ull*   wlane = (const ull*)sW + hid * 2;   // +kp*256 (+128 for B1)

    for (int t = 0; t < SJ; t++) {
        bar_pair(sg);                          // A: x_t staged, h_{t-1} visible

        ull acc[8][4];                         // (even-k sum + bias, odd-k sum)
#pragma unroll
        for (int m = 0; m < 8; m++)
#pragma unroll
            for (int g = 0; g < 4; g++) acc[m][g] = binit[g];

        // chunk = 4 k = 2 k-pairs, double-buffered
        ulonglong2 xA[8], xB[8];               // per seq: (x_k,x_k+1),(x_k+2,x_k+3)
        ulonglong2 wA[2][2], wB[2][2];         // [pair p][B0|B1]

        auto loadx = [&](ulonglong2* xq, int k) {
#pragma unroll
            for (int m = 0; m < 8; m++)
                xq[m] = *(const ulonglong2*)&xbase[m * KP + k];
        };
        auto loadw = [&](ulonglong2 (*wq)[2], int kp) {
#pragma unroll
            for (int p = 0; p < 2; p++) {
                wq[p][0] = *(const ulonglong2*)(wlane + (size_t)(kp + p) * 256);
                wq[p][1] = *(const ulonglong2*)(wlane + (size_t)(kp + p) * 256 + 128);
            }
        };
        auto chunk = [&](const ulonglong2* xq, const ulonglong2 (*wq)[2]) {
#pragma unroll
            for (int p = 0; p < 2; p++) {
#pragma unroll
                for (int m = 0; m < 8; m++) {
                    ull xh = p ? xq[m].y : xq[m].x;
                    ffma2(acc[m][0], xh, wq[p][0].x);   // gate i
                    ffma2(acc[m][1], xh, wq[p][0].y);   // gate f
                    ffma2(acc[m][2], xh, wq[p][1].x);   // gate g
                    ffma2(acc[m][3], xh, wq[p][1].y);   // gate o
                }
            }
        };

        loadx(xA, 0); loadw(wA, 0);
#pragma unroll 1
        for (int k = 0; k < KP; k += 8) {
            loadx(xB, k + 4); loadw(wB, (k + 4) >> 1);
            chunk(xA, wA);
            if (k + 8 < KP) { loadx(xA, k + 8); loadw(wA, (k + 8) >> 1); }
            chunk(xB, wB);
        }

        bar_pair(sg);                          // B: pair's reads of sXH done

#pragma unroll
        for (int m = 0; m < 8; m++) {
            float lo, hi, zi, zf, zg, zo;
            unpack2(acc[m][0], lo, hi); zi = lo + hi;
            unpack2(acc[m][1], lo, hi); zf = lo + hi;
            unpack2(acc[m][2], lo, hi); zg = lo + hi;
            unpack2(acc[m][3], lo, hi); zo = lo + hi;
            float c = sigf(zf) * cst[m] + sigf(zi) * mytanh(zg);
            cst[m] = c;
            float hv = sigf(zo) * mytanh(c);

            int s = sg * 8 + m;
            sXH[s * KP + DIN + hid] = hv;

            int q = s0 + s;
            int b = q >> 7, w = q & 127;
            int row = (DIN == 12) ? t : w;
            int col = (DIN == 12) ? w : t;
            dst[((size_t)((b * 128 + row) * 128 + col)) * 128 + dir * 64 + hid] = hv;
        }

        if (t + 1 < SJ) stage_x(t + 1);        // x region disjoint from h region
    }
}

extern "C" void kernel_launch(void* const* d_in, const int* in_sizes, int n_in,
                              void* d_out, int out_size)
{
    const float* inputs = (const float*)d_in[0];
    const float* W_ud = (const float*)d_in[1];
    const float* U_ud = (const float*)d_in[2];
    const float* b_ud = (const float*)d_in[3];
    const float* W_du = (const float*)d_in[4];
    const float* U_du = (const float*)d_in[5];
    const float* b_du = (const float*)d_in[6];
    const float* W_lr = (const float*)d_in[7];
    const float* U_lr = (const float*)d_in[8];
    const float* b_lr = (const float*)d_in[9];
    const float* W_rl = (const float*)d_in[10];
    const float* U_rl = (const float*)d_in[11];
    const float* b_rl = (const float*)d_in[12];

    float* vbuf = nullptr;
    cudaGetSymbolAddress((void**)&vbuf, g_v);

    constexpr int KP1 = 80;    // (12+64) padded to 8
    constexpr int KP2 = 192;   // 128+64
    size_t smem1 = (size_t)(KP1 * NGC + NSEQ * KP1 + NGC) * sizeof(float);  //  93,184 B
    size_t smem2 = (size_t)(KP2 * NGC + NSEQ * KP2 + NGC) * sizeof(float);  // 222,208 B

    cudaFuncSetAttribute(renet_pass<12>,  cudaFuncAttributeMaxDynamicSharedMemorySize, (int)smem1);
    cudaFuncSetAttribute(renet_pass<128>, cudaFuncAttributeMaxDynamicSharedMemorySize, (int)smem2);

    renet_pass<12><<<128, NTHR, smem1>>>(W_ud, U_ud, b_ud, W_du, U_du, b_du,
                                         inputs, vbuf);
    renet_pass<128><<<128, NTHR, smem2>>>(W_lr, U_lr, b_lr, W_rl, U_rl, b_rl,
                                          vbuf, (float*)d_out);
}

// round 10
// speedup vs baseline: 1.4240x; 1.2052x over previous
#include <cuda_runtime.h>

// ReNet layer, R9: R5 structure (column-pair f32x2, conflict-free weights,
// group-local named barriers, double-buffered chunks) widened to 512 threads:
// 8 seq-groups x 2 hid-halves, 4 seqs per group -> 4 warps/SMSP for latency
// hiding, per-warp M=4 halves register pressure (~110 regs).

#define HIDN 64
#define NGC  256
#define BN   16
#define SJ   128
#define NSEQ 32
#define NTHR 512
#define MSEQ 4        // seqs per group

typedef unsigned long long ull;

__device__ float g_v[BN * SJ * SJ * 2 * HIDN];   // vertical output [B][J][I][128]

__device__ __forceinline__ ull pack2(float lo, float hi) {
    ull r; asm("mov.b64 %0, {%1, %2};" : "=l"(r) : "f"(lo), "f"(hi)); return r;
}
__device__ __forceinline__ void unpack2(ull v, float& lo, float& hi) {
    asm("mov.b64 {%0, %1}, %2;" : "=f"(lo), "=f"(hi) : "l"(v));
}
__device__ __forceinline__ void ffma2(ull& d, ull a, ull b) {
    asm("fma.rn.f32x2 %0, %1, %2, %0;" : "+l"(d) : "l"(a), "l"(b));
}
__device__ __forceinline__ float sigf(float x)   { return 1.0f / (1.0f + __expf(-x)); }
__device__ __forceinline__ float mytanh(float x) { return 1.0f - 2.0f / (__expf(2.0f * x) + 1.0f); }
__device__ __forceinline__ void bar_grp(int sg) {
    asm volatile("bar.sync %0, 64;" :: "r"(sg + 1) : "memory");
}

template <int DIN>
__global__ void __launch_bounds__(NTHR, 1)
renet_pass(const float* __restrict__ W0, const float* __restrict__ U0, const float* __restrict__ b0,
           const float* __restrict__ W1, const float* __restrict__ U1, const float* __restrict__ b1,
           const float* __restrict__ src, float* __restrict__ dst)
{
    constexpr int K  = DIN + HIDN;
    constexpr int KP = (K + 7) & ~7;          // padded (zero weights / zero x pad)
    extern __shared__ float sm[];
    float* sWU = sm;                   // [KP][NGC]  combined W;U, gate-pair layout
    float* sXH = sm + KP * NGC;        // [NSEQ][KP] per-seq (x_t ++ h ++ pad)
    float* sB  = sXH + NSEQ * KP;      // [NGC]

    const int dir  = blockIdx.x >> 6;
    const int s0   = (blockIdx.x & 63) * NSEQ;
    const int tid  = threadIdx.x;
    const int lane = tid & 31;
    const int wid  = tid >> 5;
    const int hh   = wid & 1;                 // hid half
    const int sg   = wid >> 1;                // group: 4 seqs, 0..7
    const int ptid = tid & 63;                // thread id within group
    const int hid  = hh * 32 + lane;

    const float* W  = dir ? W1 : W0;
    const float* U  = dir ? U1 : U0;
    const float* bb = dir ? b1 : b0;

    // weight layout: sWU[k][ (h>>5)*128 + (h&31)*4 + g ] = orig[k][g*64 + h]
    // -> per (warp,k): LDS.128 at lane*16B, conflict-free; float4 = (wi,wf,wg,wo)
    for (int idx = tid; idx < KP * NGC; idx += NTHR) {
        int k = idx >> 8, c = idx & 255;
        int g = c >> 6, h = c & 63;
        int pc = (h >> 5) * 128 + (h & 31) * 4 + g;
        float v = (k < DIN) ? W[k * NGC + c]
                 : (k < K)  ? U[(k - DIN) * NGC + c] : 0.0f;
        sWU[k * NGC + pc] = v;
    }
    for (int idx = tid; idx < NGC; idx += NTHR) sB[idx] = bb[idx];
    for (int idx = tid; idx < NSEQ * (KP - DIN); idx += NTHR) {
        int s = idx / (KP - DIN), o = idx % (KP - DIN);
        sXH[s * KP + DIN + o] = 0.0f;          // h_0 = 0 and k-pad = 0
    }
    __syncthreads();

    ull binit[2];
    binit[0] = pack2(sB[0 * HIDN + hid], sB[1 * HIDN + hid]);
    binit[1] = pack2(sB[2 * HIDN + hid], sB[3 * HIDN + hid]);

    float cst[MSEQ];
#pragma unroll
    for (int p = 0; p < MSEQ; p++) cst[p] = 0.0f;

    // ---- group-local x staging for step t into rows [4sg, 4sg+4)
    auto stage_x = [&](int t) {
        if (DIN == 12) {
            const int jin = dir ? (SJ - 1 - t) : t;
            if (ptid < MSEQ * 12) {
                int sl = ptid / 12, d = ptid - sl * 12;
                int q = s0 + sg * MSEQ + sl;
                int b = q >> 7, i = q & 127;
                int pr = d / 6, rm = d - pr * 6;
                int pc = rm / 3, ch = rm - pc * 3;
                sXH[(sg * MSEQ + sl) * KP + d] =
                    src[((b * 256 + (2 * jin + pr)) * 256 + (2 * i + pc)) * 3 + ch];
            }
        } else {
            const int iin = dir ? (SJ - 1 - t) : t;
#pragma unroll
            for (int r = 0; r < 2; r++) {
                int idx = ptid + 64 * r;       // 128 = 4 seq * 32 float4
                int sl = idx >> 5, f4 = idx & 31;
                int q = s0 + sg * MSEQ + sl;
                int b = q >> 7, j = q & 127;
                float4 v4 = *(const float4*)
                    &src[((size_t)((b * 128 + j) * 128 + iin)) * 128 + f4 * 4];
                *(float4*)&sXH[(sg * MSEQ + sl) * KP + f4 * 4] = v4;
            }
        }
    };

    stage_x(0);

    const float* xbase = sXH + (sg * MSEQ) * KP;
    const float* wbase = sWU + hh * 128 + lane * 4;

    for (int t = 0; t < SJ; t++) {
        bar_grp(sg);                           // A: x_t staged, h_{t-1} visible

        ull acc[MSEQ][2];
#pragma unroll
        for (int m = 0; m < MSEQ; m++) {
            acc[m][0] = binit[0];
            acc[m][1] = binit[1];
        }

        float4 xA[MSEQ], xB[MSEQ];
        ulonglong2 wA[4], wB[4];

        auto loadx = [&](float4* xq, int k) {
#pragma unroll
            for (int m = 0; m < MSEQ; m++) xq[m] = *(const float4*)&xbase[m * KP + k];
        };
        auto loadw = [&](ulonglong2* wq, int k) {
#pragma unroll
            for (int kk = 0; kk < 4; kk++)
                wq[kk] = *(const ulonglong2*)(wbase + (k + kk) * NGC);
        };
        auto chunk = [&](const float4* xq, const ulonglong2* wq) {
#pragma unroll
            for (int kk = 0; kk < 4; kk++) {
#pragma unroll
                for (int m = 0; m < MSEQ; m++) {
                    float a = ((const float*)&xq[m])[kk];
                    ull a2 = pack2(a, a);
                    ffma2(acc[m][0], a2, wq[kk].x);   // (zi, zf)
                    ffma2(acc[m][1], a2, wq[kk].y);   // (zg, zo)
                }
            }
        };

        loadx(xA, 0); loadw(wA, 0);
#pragma unroll 1
        for (int k = 0; k < KP; k += 8) {
            loadx(xB, k + 4); loadw(wB, k + 4);
            chunk(xA, wA);
            if (k + 8 < KP) { loadx(xA, k + 8); loadw(wA, k + 8); }
            chunk(xB, wB);
        }

        bar_grp(sg);                           // B: group's reads of sXH done

        // ---- gates, state update, h write-back + global store
#pragma unroll
        for (int m = 0; m < MSEQ; m++) {
            float zi, zf, zg, zo;
            unpack2(acc[m][0], zi, zf);
            unpack2(acc[m][1], zg, zo);
            float c = sigf(zf) * cst[m] + sigf(zi) * mytanh(zg);
            cst[m] = c;
            float hv = sigf(zo) * mytanh(c);

            int s = sg * MSEQ + m;
            sXH[s * KP + DIN + hid] = hv;

            int q = s0 + s;
            int b = q >> 7, w = q & 127;
            int row = (DIN == 12) ? t : w;
            int col = (DIN == 12) ? w : t;
            dst[((size_t)((b * 128 + row) * 128 + col)) * 128 + dir * 64 + hid] = hv;
        }

        if (t + 1 < SJ) stage_x(t + 1);        // x region disjoint from h region
    }
}

extern "C" void kernel_launch(void* const* d_in, const int* in_sizes, int n_in,
                              void* d_out, int out_size)
{
    const float* inputs = (const float*)d_in[0];
    const float* W_ud = (const float*)d_in[1];
    const float* U_ud = (const float*)d_in[2];
    const float* b_ud = (const float*)d_in[3];
    const float* W_du = (const float*)d_in[4];
    const float* U_du = (const float*)d_in[5];
    const float* b_du = (const float*)d_in[6];
    const float* W_lr = (const float*)d_in[7];
    const float* U_lr = (const float*)d_in[8];
    const float* b_lr = (const float*)d_in[9];
    const float* W_rl = (const float*)d_in[10];
    const float* U_rl = (const float*)d_in[11];
    const float* b_rl = (const float*)d_in[12];

    float* vbuf = nullptr;
    cudaGetSymbolAddress((void**)&vbuf, g_v);

    constexpr int KP1 = 80;    // (12+64) padded to 8
    constexpr int KP2 = 192;   // 128+64
    size_t smem1 = (size_t)(KP1 * NGC + NSEQ * KP1 + NGC) * sizeof(float);  //  93,184 B
    size_t smem2 = (size_t)(KP2 * NGC + NSEQ * KP2 + NGC) * sizeof(float);  // 222,208 B

    cudaFuncSetAttribute(renet_pass<12>,  cudaFuncAttributeMaxDynamicSharedMemorySize, (int)smem1);
    cudaFuncSetAttribute(renet_pass<128>, cudaFuncAttributeMaxDynamicSharedMemorySize, (int)smem2);

    renet_pass<12><<<128, NTHR, smem1>>>(W_ud, U_ud, b_ud, W_du, U_du, b_du,
                                         inputs, vbuf);
    renet_pass<128><<<128, NTHR, smem2>>>(W_lr, U_lr, b_lr, W_rl, U_rl, b_rl,
                                          vbuf, (float*)d_out);
}